// round 2
// baseline (speedup 1.0000x reference)
#include <cuda_runtime.h>
#include <cstdint>
#include <math.h>

// Problem constants (fixed shapes)
#define N_ST   2048
#define N_OBS  8192
#define T_LEN  8192

#define N_BLOCKS        128
#define COLS_PER_BLOCK  16          // 2048 / 128
#define THREADS         256

// ---- persistent device scratch (no allocations allowed) ----
__device__ float              g_Bobs[(size_t)T_LEN * N_ST];   // 64 MB: Bobs[t][i] = B[i][se[t]]
__device__ float              g_alpha[2][N_ST];               // double-buffered alpha
__device__ unsigned long long g_flags[N_BLOCKS];              // monotonic per-CTA step counters (zero-init)

// Shared memory layout (dynamic):
//   float4 As4[2048*4]   : 131072 B   A[:, colbase:colbase+16] as float4 groups, row-major
//   float  alpha_s[2048] :   8192 B
//   float  red[128]      :    512 B   cross-warp reduction scratch
//   u64    sbase         :      8 B
#define SMEM_AS_BYTES   (N_ST * 4 * 16)
#define SMEM_BYTES      (SMEM_AS_BYTES + N_ST * 4 + 128 * 4 + 16)

// ---------------------------------------------------------------------------
// Kernel 1: gather emission probabilities  Bobs[t][i] = B[i*N_OBS + se[t]]
// ---------------------------------------------------------------------------
__global__ void gather_bobs(const float* __restrict__ B, const int* __restrict__ se) {
    size_t idx    = (size_t)blockIdx.x * blockDim.x + threadIdx.x;
    size_t stride = (size_t)gridDim.x * blockDim.x;
    const size_t total = (size_t)T_LEN * N_ST;
    for (; idx < total; idx += stride) {
        int t = (int)(idx >> 11);          // / N_ST
        int i = (int)(idx & (N_ST - 1));   // % N_ST
        g_Bobs[idx] = B[(size_t)i * N_OBS + se[t]];
    }
}

// ---------------------------------------------------------------------------
// Kernel 2: persistent forward recursion.
// CTA b owns output columns [16b, 16b+16). A slice lives in SMEM.
// Per step: poll flags -> copy alpha (L2, .cv) -> SMEM matvec -> stcg chunk
//           -> threadfence -> bump flag.
// ---------------------------------------------------------------------------
extern __shared__ unsigned char smem_raw[];

__global__ void __launch_bounds__(THREADS, 1)
hmm_forward(const float* __restrict__ Pi0,
            const float* __restrict__ A,
            float* __restrict__ out)
{
    float4* As4     = (float4*)smem_raw;
    float*  alpha_s = (float*)(smem_raw + SMEM_AS_BYTES);
    float*  red     = alpha_s + N_ST;
    unsigned long long* sbase = (unsigned long long*)(red + 128);

    const int tid     = threadIdx.x;
    const int b       = blockIdx.x;
    const int colbase = b * COLS_PER_BLOCK;
    const int lane    = tid & 31;
    const int warp    = tid >> 5;
    const int c       = tid & 3;   // float4 group within the 16-col slice
    const int s       = tid >> 2;  // j-stripe id, 0..63

    // ---- one-time: load A slice into SMEM (float4 per (row j, group c)) ----
    for (int idx = tid; idx < N_ST * 4; idx += THREADS) {
        int j = idx >> 2, g = idx & 3;
        As4[idx] = *(const float4*)(A + (size_t)j * N_ST + colbase + (g << 2));
    }

    // ---- read persistent flag base (all flags equal at launch boundary) ----
    if (tid == 0) *sbase = *(volatile unsigned long long*)&g_flags[b];
    __syncthreads();
    const unsigned long long base = *sbase;

    // ---- step 0: alpha0 = Pi0 * Bobs[0] ----
    if (tid < COLS_PER_BLOCK) {
        int i = colbase + tid;
        __stcg(&g_alpha[0][i], Pi0[i] * g_Bobs[i]);
    }
    __syncthreads();
    __threadfence();
    if (tid == 0) *(volatile unsigned long long*)&g_flags[b] = base + 1;

    // ---- steps 1 .. T-1 ----
    for (int t = 1; t < T_LEN; ++t) {
        const unsigned long long tgt = base + (unsigned long long)t;

        // wait for every CTA's step-(t-1) chunk
        if (tid < 32) {
            const volatile unsigned long long* vf = g_flags;
            bool ok;
            do {
                ok = (vf[tid]      >= tgt) & (vf[tid + 32] >= tgt) &
                     (vf[tid + 64] >= tgt) & (vf[tid + 96] >= tgt);
            } while (!__all_sync(0xffffffffu, ok));
            __threadfence();   // order flag observation before data loads
        }
        __syncthreads();

        // copy alpha_{t-1} (L2-coherent .cv loads, 2 float4 per thread)
        {
            const float4* src = (const float4*)g_alpha[(t - 1) & 1];
            float4 v0 = __ldcv(src + tid);
            float4 v1 = __ldcv(src + tid + THREADS);
            ((float4*)alpha_s)[tid]           = v0;
            ((float4*)alpha_s)[tid + THREADS] = v1;
        }

        // prefetch this step's emission weights for our 16 columns
        float bt = 0.0f;
        if (tid < COLS_PER_BLOCK)
            bt = __ldg(&g_Bobs[(size_t)t * N_ST + colbase + tid]);
        __syncthreads();

        // matvec partial: acc[e] = sum over j in {s + 64k} of alpha[j]*A[j][4c+e]
        float4 acc = make_float4(0.f, 0.f, 0.f, 0.f);
        #pragma unroll 8
        for (int k = 0; k < N_ST / 64; ++k) {
            int j = s + (k << 6);
            float a   = alpha_s[j];
            float4 av = As4[(j << 2) + c];
            acc.x = fmaf(a, av.x, acc.x);
            acc.y = fmaf(a, av.y, acc.y);
            acc.z = fmaf(a, av.z, acc.z);
            acc.w = fmaf(a, av.w, acc.w);
        }

        // butterfly-reduce over the 8 lanes sharing the same c (bits 2..4)
        #pragma unroll
        for (int off = 4; off < 32; off <<= 1) {
            acc.x += __shfl_xor_sync(0xffffffffu, acc.x, off);
            acc.y += __shfl_xor_sync(0xffffffffu, acc.y, off);
            acc.z += __shfl_xor_sync(0xffffffffu, acc.z, off);
            acc.w += __shfl_xor_sync(0xffffffffu, acc.w, off);
        }
        if (lane < 4) {   // lane == c here
            int o = (warp << 4) + (lane << 2);
            red[o + 0] = acc.x;
            red[o + 1] = acc.y;
            red[o + 2] = acc.z;
            red[o + 3] = acc.w;
        }
        __syncthreads();

        // final per-column sum over 8 warps, apply emission, publish
        if (tid < COLS_PER_BLOCK) {
            float sum = 0.f;
            #pragma unroll
            for (int w = 0; w < 8; ++w) sum += red[(w << 4) + tid];
            __stcg(&g_alpha[t & 1][colbase + tid], sum * bt);
        }
        __syncthreads();
        __threadfence();
        if (tid == 0) *(volatile unsigned long long*)&g_flags[b] = base + (unsigned long long)t + 1;
    }

    // ---- final reduction by CTA 0 ----
    if (b == 0) {
        const unsigned long long tgt = base + (unsigned long long)T_LEN;
        if (tid < 32) {
            const volatile unsigned long long* vf = g_flags;
            bool ok;
            do {
                ok = (vf[tid]      >= tgt) & (vf[tid + 32] >= tgt) &
                     (vf[tid + 64] >= tgt) & (vf[tid + 96] >= tgt);
            } while (!__all_sync(0xffffffffu, ok));
            __threadfence();
        }
        __syncthreads();

        const float* src = g_alpha[(T_LEN - 1) & 1];
        float ssum = 0.f;
        for (int i = tid; i < N_ST; i += THREADS) ssum += __ldcv(&src[i]);
        #pragma unroll
        for (int off = 16; off > 0; off >>= 1)
            ssum += __shfl_xor_sync(0xffffffffu, ssum, off);
        if (lane == 0) red[warp] = ssum;
        __syncthreads();
        if (tid == 0) {
            float tot = 0.f;
            #pragma unroll
            for (int w = 0; w < 8; ++w) tot += red[w];
            out[0] = -logf(tot);
        }
    }
}

// ---------------------------------------------------------------------------
// Launch wrapper. Inputs (metadata order): Pi_0 [2048] f32, A [2048*2048] f32,
// B [2048*8192] f32, se [8192] i32. Output: 1 x f32.
// ---------------------------------------------------------------------------
extern "C" void kernel_launch(void* const* d_in, const int* in_sizes, int n_in,
                              void* d_out, int out_size) {
    const float* Pi0 = (const float*)d_in[0];
    const float* A   = (const float*)d_in[1];
    const float* B   = (const float*)d_in[2];
    const int*   se  = (const int*)d_in[3];
    float*       out = (float*)d_out;

    (void)in_sizes; (void)n_in; (void)out_size;

    cudaFuncSetAttribute(hmm_forward,
                         cudaFuncAttributeMaxDynamicSharedMemorySize,
                         SMEM_BYTES);

    gather_bobs<<<2048, 256>>>(B, se);
    hmm_forward<<<N_BLOCKS, THREADS, SMEM_BYTES>>>(Pi0, A, out);
}

// round 3
// speedup vs baseline: 3.2396x; 3.2396x over previous
#include <cuda_runtime.h>
#include <cstdint>
#include <math.h>

// Problem constants (fixed shapes)
#define N_ST   2048
#define N_OBS  8192
#define T_LEN  8192

#define N_BLOCKS        128
#define COLS_PER_BLOCK  16          // 2048 / 128
#define THREADS         256
#define KITER           32          // j-values per thread (32 * 64 stripes = 2048)

// ---- persistent device scratch (no allocations allowed) ----
__device__ float              g_Bobs[(size_t)T_LEN * N_ST];   // 64 MB: Bobs[t][i] = B[i][se[t]]
__device__ float              g_alpha[2][N_ST];               // double-buffered alpha
__device__ unsigned long long g_count;                        // aggregated step counter (reset to 0 each run)

// ---------------------------------------------------------------------------
// Kernel 1: gather emission probabilities  Bobs[t][i] = B[i*N_OBS + se[t]]
// ---------------------------------------------------------------------------
__global__ void gather_bobs(const float* __restrict__ B, const int* __restrict__ se) {
    size_t idx    = (size_t)blockIdx.x * blockDim.x + threadIdx.x;
    size_t stride = (size_t)gridDim.x * blockDim.x;
    const size_t total = (size_t)T_LEN * N_ST;
    for (; idx < total; idx += stride) {
        int t = (int)(idx >> 11);          // / N_ST
        int i = (int)(idx & (N_ST - 1));   // % N_ST
        g_Bobs[idx] = B[(size_t)i * N_OBS + se[t]];
    }
}

// ---------------------------------------------------------------------------
// Sync primitives
// ---------------------------------------------------------------------------
__device__ __forceinline__ unsigned long long ld_acquire_u64(const unsigned long long* p) {
    unsigned long long v;
    asm volatile("ld.acquire.gpu.global.u64 %0, [%1];" : "=l"(v) : "l"(p) : "memory");
    return v;
}
__device__ __forceinline__ void red_release_add_u64(unsigned long long* p, unsigned long long v) {
    asm volatile("red.release.gpu.global.add.u64 [%0], %1;" :: "l"(p), "l"(v) : "memory");
}

// ---------------------------------------------------------------------------
// Kernel 2: persistent forward recursion. CTA b owns output columns
// [16b, 16b+16). Its A-slice lives in REGISTERS (32 x float4 per thread).
// Thread layout: c = tid&3 -> column group (4 cols), q = tid>>2 -> j-stripe;
// thread covers j = q + 64k, k = 0..31.
// ---------------------------------------------------------------------------
__global__ void __launch_bounds__(THREADS, 1)
hmm_forward(const float* __restrict__ Pi0,
            const float* __restrict__ A,
            float* __restrict__ out)
{
    __shared__ float alpha_s[N_ST];
    __shared__ float red_s[8 * COLS_PER_BLOCK];   // [warp][16 cols]

    const int tid     = threadIdx.x;
    const int b       = blockIdx.x;
    const int colbase = b * COLS_PER_BLOCK;
    const int lane    = tid & 31;
    const int warp    = tid >> 5;
    const int c       = tid & 3;    // float4 column group (cols 4c..4c+3)
    const int q       = tid >> 2;   // j-stripe id, 0..63

    // ---- one-time: load A slice into registers ----
    float4 Areg[KITER];
    #pragma unroll
    for (int k = 0; k < KITER; ++k) {
        int j = q + (k << 6);
        Areg[k] = *(const float4*)(A + (size_t)j * N_ST + colbase + (c << 2));
    }

    // ---- step 0: alpha0 = Pi0 * Bobs[0] ----
    if (tid < COLS_PER_BLOCK) {
        int i = colbase + tid;
        __stcg(&g_alpha[0][i], Pi0[i] * g_Bobs[i]);
    }
    __syncthreads();
    if (tid == 0) {
        __threadfence();
        red_release_add_u64(&g_count, 1ull);
    }

    // ---- steps 1 .. T-1 ----
    for (int t = 1; t < T_LEN; ++t) {
        // emission weights for this step do NOT depend on alpha -> issue early
        float bt = 0.0f;
        if (tid < COLS_PER_BLOCK)
            bt = __ldg(&g_Bobs[(size_t)t * N_ST + colbase + tid]);

        // wait until all 128 CTAs published step t-1
        const unsigned long long tgt = (unsigned long long)t * N_BLOCKS;
        if (tid == 0) {
            while (ld_acquire_u64(&g_count) < tgt) { }
        }
        __syncthreads();

        // stage alpha_{t-1} into SMEM (L2-coherent loads)
        {
            const float4* src = (const float4*)g_alpha[(t - 1) & 1];
            float4 v0 = __ldcv(src + tid);
            float4 v1 = __ldcv(src + tid + THREADS);
            ((float4*)alpha_s)[tid]           = v0;
            ((float4*)alpha_s)[tid + THREADS] = v1;
        }
        __syncthreads();

        // matvec partial: acc[e] += alpha[q+64k] * A[q+64k][4c+e]  (A in regs)
        float4 acc = make_float4(0.f, 0.f, 0.f, 0.f);
        #pragma unroll
        for (int k = 0; k < KITER; ++k) {
            float a = alpha_s[q + (k << 6)];
            acc.x = fmaf(a, Areg[k].x, acc.x);
            acc.y = fmaf(a, Areg[k].y, acc.y);
            acc.z = fmaf(a, Areg[k].z, acc.z);
            acc.w = fmaf(a, Areg[k].w, acc.w);
        }

        // reduce across the 8 lanes sharing the same c (xor over bits 2..4)
        #pragma unroll
        for (int off = 4; off < 32; off <<= 1) {
            acc.x += __shfl_xor_sync(0xffffffffu, acc.x, off);
            acc.y += __shfl_xor_sync(0xffffffffu, acc.y, off);
            acc.z += __shfl_xor_sync(0xffffffffu, acc.z, off);
            acc.w += __shfl_xor_sync(0xffffffffu, acc.w, off);
        }
        if (lane < 4) {   // lane == c here
            int o = (warp << 4) + (lane << 2);
            red_s[o + 0] = acc.x;
            red_s[o + 1] = acc.y;
            red_s[o + 2] = acc.z;
            red_s[o + 3] = acc.w;
        }
        __syncthreads();

        // final per-column sum over 8 warps, apply emission, publish
        if (tid < COLS_PER_BLOCK) {
            float sum = 0.f;
            #pragma unroll
            for (int w = 0; w < 8; ++w) sum += red_s[(w << 4) + tid];
            __stcg(&g_alpha[t & 1][colbase + tid], sum * bt);
        }
        __syncthreads();
        if (tid == 0) {
            __threadfence();
            red_release_add_u64(&g_count, 1ull);
        }
    }

    // ---- final reduction + counter reset by CTA 0 ----
    if (b == 0) {
        const unsigned long long tgt = (unsigned long long)T_LEN * N_BLOCKS;
        if (tid == 0) {
            while (ld_acquire_u64(&g_count) < tgt) { }
        }
        __syncthreads();

        const float* src = g_alpha[(T_LEN - 1) & 1];
        float ssum = 0.f;
        for (int i = tid; i < N_ST; i += THREADS) ssum += __ldcv(&src[i]);
        #pragma unroll
        for (int off = 16; off > 0; off >>= 1)
            ssum += __shfl_xor_sync(0xffffffffu, ssum, off);
        if (lane == 0) red_s[warp] = ssum;
        __syncthreads();
        if (tid == 0) {
            float tot = 0.f;
            #pragma unroll
            for (int w = 0; w < 8; ++w) tot += red_s[w];
            out[0] = -logf(tot);
            // reset counter for the next graph replay (all increments observed)
            *((volatile unsigned long long*)&g_count) = 0ull;
        }
    }
}

// ---------------------------------------------------------------------------
// Launch wrapper. Inputs (metadata order): Pi_0 [2048] f32, A [2048*2048] f32,
// B [2048*8192] f32, se [8192] i32. Output: 1 x f32.
// ---------------------------------------------------------------------------
extern "C" void kernel_launch(void* const* d_in, const int* in_sizes, int n_in,
                              void* d_out, int out_size) {
    const float* Pi0 = (const float*)d_in[0];
    const float* A   = (const float*)d_in[1];
    const float* B   = (const float*)d_in[2];
    const int*   se  = (const int*)d_in[3];
    float*       out = (float*)d_out;

    (void)in_sizes; (void)n_in; (void)out_size;

    gather_bobs<<<2048, 256>>>(B, se);
    hmm_forward<<<N_BLOCKS, THREADS>>>(Pi0, A, out);
}